// round 14
// baseline (speedup 1.0000x reference)
#include <cuda_runtime.h>

// LocallyConnectedGC: out[b,m,f] = bias[f] + sum_n x[b,n,f] * (support*kernel)[n,m]
// support = 3-hop ring reachability -> banded W, 7 taps: n in {m-3..m+3} mod 199.
//
// R2: register sliding window over M_TILE=8 consecutive output nodes per block.
// Cuts L1 load wavefronts 56 -> 14 per 8 outputs (R1 was L1tex-bound at 85.9%).

#define N_NODES 199
#define N_FEAT  1024
#define N_BATCH 256
#define HALO    3
#define TAPS    (2 * HALO + 1)   // 7
#define M_TILE  8
#define TILES_PER_B ((N_NODES + M_TILE - 1) / M_TILE)   // 25

__global__ __launch_bounds__(256, 4)
void lcgc_window_kernel(const float* __restrict__ x,
                        const float* __restrict__ support,
                        const float* __restrict__ kernel,
                        const float* __restrict__ bias,
                        float* __restrict__ out)
{
    const int bt   = blockIdx.x;
    const int tile = bt % TILES_PER_B;
    const int b    = bt / TILES_PER_B;
    const int m0   = tile * M_TILE;
    const int f4   = threadIdx.x << 2;    // 256 threads * float4 = 1024 feats

    const float* __restrict__ xb = x + (size_t)b * (N_NODES * N_FEAT);

    const float4 bv = *reinterpret_cast<const float4*>(bias + f4);

    // Initial window: rows (m0-3 .. m0+3) mod 199
    float4 win[TAPS];
#pragma unroll
    for (int d = 0; d < TAPS; d++) {
        int n = m0 - HALO + d;
        if (n < 0)        n += N_NODES;
        if (n >= N_NODES) n -= N_NODES;
        win[d] = *reinterpret_cast<const float4*>(xb + (size_t)n * N_FEAT + f4);
    }

#pragma unroll
    for (int i = 0; i < M_TILE; i++) {
        const int m = m0 + i;
        const bool valid = (m < N_NODES);

        if (valid) {
            // 7 tap weights for output column m (uniform per block -> broadcast)
            float4 acc = bv;
#pragma unroll
            for (int d = 0; d < TAPS; d++) {
                int n = m - HALO + d;
                if (n < 0)        n += N_NODES;
                if (n >= N_NODES) n -= N_NODES;
                const int idx = n * N_NODES + m;
                const float wd = support[idx] * kernel[idx];
                acc.x = fmaf(win[d].x, wd, acc.x);
                acc.y = fmaf(win[d].y, wd, acc.y);
                acc.z = fmaf(win[d].z, wd, acc.z);
                acc.w = fmaf(win[d].w, wd, acc.w);
            }
            *reinterpret_cast<float4*>(out + ((size_t)b * N_NODES + m) * N_FEAT + f4) = acc;
        }

        // Slide window: bring in row (m+1)+3 for the next output
        if (i < M_TILE - 1) {
#pragma unroll
            for (int d = 0; d < TAPS - 1; d++) win[d] = win[d + 1];
            if (m + 1 < N_NODES) {
                int n = m + 1 + HALO;
                if (n >= N_NODES) n -= N_NODES;
                win[TAPS - 1] = *reinterpret_cast<const float4*>(xb + (size_t)n * N_FEAT + f4);
            }
        }
    }
}

extern "C" void kernel_launch(void* const* d_in, const int* in_sizes, int n_in,
                              void* d_out, int out_size)
{
    const float* x       = (const float*)d_in[0];
    const float* support = (const float*)d_in[1];
    const float* kernel  = (const float*)d_in[2];
    const float* bias    = (const float*)d_in[3];
    float*       out     = (float*)d_out;

    const dim3 grid(N_BATCH * TILES_PER_B);
    const dim3 block(256);
    lcgc_window_kernel<<<grid, block>>>(x, support, kernel, bias, out);
}

// round 15
// speedup vs baseline: 1.0312x; 1.0312x over previous
#include <cuda_runtime.h>

// LocallyConnectedGC: out[b,m,f] = bias[f] + sum_n x[b,n,f] * (support*kernel)[n,m]
// support = 3-hop ring reachability -> banded W, 7 taps: n in {m-3..m+3} mod 199.
//
// R2: register sliding window over M_TILE=8 consecutive output nodes per block.
// Cuts L1 load wavefronts 56 -> 14 per 8 outputs (R1 was L1tex-bound at 85.9%).

#define N_NODES 199
#define N_FEAT  1024
#define N_BATCH 256
#define HALO    3
#define TAPS    (2 * HALO + 1)   // 7
#define M_TILE  8
#define TILES_PER_B ((N_NODES + M_TILE - 1) / M_TILE)   // 25

__global__ __launch_bounds__(256, 4)
void lcgc_window_kernel(const float* __restrict__ x,
                        const float* __restrict__ support,
                        const float* __restrict__ kernel,
                        const float* __restrict__ bias,
                        float* __restrict__ out)
{
    const int bt   = blockIdx.x;
    const int tile = bt % TILES_PER_B;
    const int b    = bt / TILES_PER_B;
    const int m0   = tile * M_TILE;
    const int f4   = threadIdx.x << 2;    // 256 threads * float4 = 1024 feats

    const float* __restrict__ xb = x + (size_t)b * (N_NODES * N_FEAT);

    const float4 bv = *reinterpret_cast<const float4*>(bias + f4);

    // Initial window: rows (m0-3 .. m0+3) mod 199
    float4 win[TAPS];
#pragma unroll
    for (int d = 0; d < TAPS; d++) {
        int n = m0 - HALO + d;
        if (n < 0)        n += N_NODES;
        if (n >= N_NODES) n -= N_NODES;
        win[d] = *reinterpret_cast<const float4*>(xb + (size_t)n * N_FEAT + f4);
    }

#pragma unroll
    for (int i = 0; i < M_TILE; i++) {
        const int m = m0 + i;
        const bool valid = (m < N_NODES);

        if (valid) {
            // 7 tap weights for output column m (uniform per block -> broadcast)
            float4 acc = bv;
#pragma unroll
            for (int d = 0; d < TAPS; d++) {
                int n = m - HALO + d;
                if (n < 0)        n += N_NODES;
                if (n >= N_NODES) n -= N_NODES;
                const int idx = n * N_NODES + m;
                const float wd = support[idx] * kernel[idx];
                acc.x = fmaf(win[d].x, wd, acc.x);
                acc.y = fmaf(win[d].y, wd, acc.y);
                acc.z = fmaf(win[d].z, wd, acc.z);
                acc.w = fmaf(win[d].w, wd, acc.w);
            }
            *reinterpret_cast<float4*>(out + ((size_t)b * N_NODES + m) * N_FEAT + f4) = acc;
        }

        // Slide window: bring in row (m+1)+3 for the next output
        if (i < M_TILE - 1) {
#pragma unroll
            for (int d = 0; d < TAPS - 1; d++) win[d] = win[d + 1];
            if (m + 1 < N_NODES) {
                int n = m + 1 + HALO;
                if (n >= N_NODES) n -= N_NODES;
                win[TAPS - 1] = *reinterpret_cast<const float4*>(xb + (size_t)n * N_FEAT + f4);
            }
        }
    }
}

extern "C" void kernel_launch(void* const* d_in, const int* in_sizes, int n_in,
                              void* d_out, int out_size)
{
    const float* x       = (const float*)d_in[0];
    const float* support = (const float*)d_in[1];
    const float* kernel  = (const float*)d_in[2];
    const float* bias    = (const float*)d_in[3];
    float*       out     = (float*)d_out;

    const dim3 grid(N_BATCH * TILES_PER_B);
    const dim3 block(256);
    lcgc_window_kernel<<<grid, block>>>(x, support, kernel, bias, out);
}